// round 4
// baseline (speedup 1.0000x reference)
#include <cuda_runtime.h>
#include <cuda_bf16.h>

#define HW     8192
#define THRESH 0.5f
#define RAD    4
#define TX     128     // output tile cols per block
#define TY     64      // output tile rows per block
#define IN_W   144     // loaded cols: TX + 16 (aligned halo: -8 .. +136)
#define IN_H   72      // loaded rows: TY + 8
#define NTHREADS 256

// smem layout: in_s[IN_H][IN_W], h_s[IN_H][TX]
#define SMEM_FLOATS (IN_H*IN_W + IN_H*TX)

__device__ __forceinline__ float4 f4max(float4 a, float4 b) {
    float4 r;
    r.x = fmaxf(a.x, b.x); r.y = fmaxf(a.y, b.y);
    r.z = fmaxf(a.z, b.z); r.w = fmaxf(a.w, b.w);
    return r;
}

__global__ void __launch_bounds__(NTHREADS, 2)
postprocess_kernel(const float* __restrict__ in, float* __restrict__ out)
{
    extern __shared__ float smem[];
    float* in_s = smem;                 // IN_H x IN_W
    float* h_s  = smem + IN_H * IN_W;   // IN_H x TX

    const int bx = blockIdx.x;          // 0..63
    const int by = blockIdx.y;          // 0..127
    const int tid = threadIdx.x;

    const int gr0 = by * TY - RAD;      // first loaded global row
    const int gc0 = bx * TX - 8;        // first loaded global col (16B aligned)

    // ---------------- Phase 1: load + threshold into smem ----------------
    // IN_H rows x (IN_W/4 = 36) float4s = 2592 vector loads
    for (int idx = tid; idx < IN_H * (IN_W / 4); idx += NTHREADS) {
        const int row  = idx / (IN_W / 4);
        const int col4 = (idx - row * (IN_W / 4)) * 4;
        const int gr = gr0 + row;
        const int gc = gc0 + col4;
        float4 v = make_float4(0.f, 0.f, 0.f, 0.f);
        if ((unsigned)gr < (unsigned)HW) {
            if (gc >= 0 && gc + 3 < HW) {
                v = *reinterpret_cast<const float4*>(&in[(size_t)gr * HW + gc]);
            } else {
                const float* rp = &in[(size_t)gr * HW];
                if ((unsigned)(gc + 0) < (unsigned)HW) v.x = rp[gc + 0];
                if ((unsigned)(gc + 1) < (unsigned)HW) v.y = rp[gc + 1];
                if ((unsigned)(gc + 2) < (unsigned)HW) v.z = rp[gc + 2];
                if ((unsigned)(gc + 3) < (unsigned)HW) v.w = rp[gc + 3];
            }
        }
        // threshold: keep strictly-above, else 0
        v.x = (v.x > THRESH) ? v.x : 0.f;
        v.y = (v.y > THRESH) ? v.y : 0.f;
        v.z = (v.z > THRESH) ? v.z : 0.f;
        v.w = (v.w > THRESH) ? v.w : 0.f;
        *reinterpret_cast<float4*>(&in_s[row * IN_W + col4]) = v;
    }
    __syncthreads();

    // ---------------- Phase 2: horizontal 9-max ----------------
    // For output col c (0..TX-1): window = in_s cols [c+4, c+12]
    // Process 4 outputs per thread-task using 3 float4 reads.
    for (int idx = tid; idx < IN_H * (TX / 4); idx += NTHREADS) {
        const int row = idx / (TX / 4);
        const int c   = (idx - row * (TX / 4)) * 4;
        const float* rp = &in_s[row * IN_W];
        const float4 a = *reinterpret_cast<const float4*>(&rp[c + 4]);
        const float4 b = *reinterpret_cast<const float4*>(&rp[c + 8]);
        const float4 d = *reinterpret_cast<const float4*>(&rp[c + 12]);
        // suffix maxes of a
        const float s3 = a.w;
        const float s2 = fmaxf(a.z, s3);
        const float s1 = fmaxf(a.y, s2);
        const float s0 = fmaxf(a.x, s1);
        // full max of b (shared by all four)
        const float mb = fmaxf(fmaxf(b.x, b.y), fmaxf(b.z, b.w));
        // prefix maxes of d
        const float p0 = d.x;
        const float p1 = fmaxf(p0, d.y);
        const float p2 = fmaxf(p1, d.z);
        const float p3 = fmaxf(p2, d.w);
        float4 o;
        o.x = fmaxf(fmaxf(s0, mb), p0);
        o.y = fmaxf(fmaxf(s1, mb), p1);
        o.z = fmaxf(fmaxf(s2, mb), p2);
        o.w = fmaxf(fmaxf(s3, mb), p3);
        *reinterpret_cast<float4*>(&h_s[row * TX + c]) = o;
    }
    __syncthreads();

    // ---------------- Phase 3: vertical 9-max + peak epilogue ----------------
    // 256 tasks: 32 col-groups (4 cols each) x 8 row-strips (8 rows each).
    {
        const int cg    = tid & 31;        // 0..31
        const int strip = tid >> 5;        // 0..7
        const int c  = cg * 4;
        const int r0 = strip * 8;

        // Load h_s rows r0 .. r0+15 (block A = first 8, block B = next 8)
        float4 hv[16];
#pragma unroll
        for (int j = 0; j < 16; j++)
            hv[j] = *reinterpret_cast<const float4*>(&h_s[(r0 + j) * TX + c]);

        // suffix maxes over block A in place: hv[i] = max(h[i..7])
#pragma unroll
        for (int i = 6; i >= 0; i--)
            hv[i] = f4max(hv[i], hv[i + 1]);

        float4 p = hv[8];  // running prefix max over block B
        const size_t gc = (size_t)(bx * TX + c);
#pragma unroll
        for (int r = 0; r < 8; r++) {
            if (r > 0) p = f4max(p, hv[8 + r]);
            const float4 mp = f4max(hv[r], p);   // 9-tap vertical max
            const float4 ctr = *reinterpret_cast<const float4*>(
                &in_s[(r0 + r + RAD) * IN_W + (c + 8)]);
            float4 o;
            o.x = (mp.x > 0.f && mp.x == ctr.x) ? mp.x : 0.f;
            o.y = (mp.y > 0.f && mp.y == ctr.y) ? mp.y : 0.f;
            o.z = (mp.z > 0.f && mp.z == ctr.z) ? mp.z : 0.f;
            o.w = (mp.w > 0.f && mp.w == ctr.w) ? mp.w : 0.f;
            const size_t grow = (size_t)(by * TY + r0 + r);
            *reinterpret_cast<float4*>(&out[grow * HW + gc]) = o;
        }
    }
}

extern "C" void kernel_launch(void* const* d_in, const int* in_sizes, int n_in,
                              void* d_out, int out_size)
{
    const float* in = (const float*)d_in[0];
    float* out = (float*)d_out;

    static bool attr_set = false;
    if (!attr_set) {
        cudaFuncSetAttribute(postprocess_kernel,
                             cudaFuncAttributeMaxDynamicSharedMemorySize,
                             SMEM_FLOATS * (int)sizeof(float));
        attr_set = true;
    }

    dim3 grid(HW / TX, HW / TY);   // 64 x 128
    postprocess_kernel<<<grid, NTHREADS, SMEM_FLOATS * sizeof(float)>>>(in, out);
}

// round 5
// speedup vs baseline: 1.0257x; 1.0257x over previous
#include <cuda_runtime.h>
#include <cuda_bf16.h>

#define HW     8192
#define THRESH 0.5f
#define RAD    4
#define TX     128     // output tile cols per block
#define TY     64      // output tile rows per block
#define IN_W   144     // loaded cols: TX + 16 (aligned halo: -8 .. +136)
#define IN_H   72      // loaded rows: TY + 8
#define NTHREADS 256

// smem layout: in_s[IN_H][IN_W], h_s[IN_H][TX]
#define SMEM_FLOATS (IN_H*IN_W + IN_H*TX)

__device__ __forceinline__ float4 f4max(float4 a, float4 b) {
    float4 r;
    r.x = fmaxf(a.x, b.x); r.y = fmaxf(a.y, b.y);
    r.z = fmaxf(a.z, b.z); r.w = fmaxf(a.w, b.w);
    return r;
}

__global__ void __launch_bounds__(NTHREADS, 2)
postprocess_kernel(const float* __restrict__ in, float* __restrict__ out)
{
    extern __shared__ float smem[];
    float* in_s = smem;                 // IN_H x IN_W
    float* h_s  = smem + IN_H * IN_W;   // IN_H x TX

    const int bx = blockIdx.x;          // 0..63
    const int by = blockIdx.y;          // 0..127
    const int tid = threadIdx.x;

    const int gr0 = by * TY - RAD;      // first loaded global row
    const int gc0 = bx * TX - 8;        // first loaded global col (16B aligned)

    // ---------------- Phase 1: load + threshold into smem ----------------
    // IN_H rows x (IN_W/4 = 36) float4s = 2592 vector loads
    for (int idx = tid; idx < IN_H * (IN_W / 4); idx += NTHREADS) {
        const int row  = idx / (IN_W / 4);
        const int col4 = (idx - row * (IN_W / 4)) * 4;
        const int gr = gr0 + row;
        const int gc = gc0 + col4;
        float4 v = make_float4(0.f, 0.f, 0.f, 0.f);
        if ((unsigned)gr < (unsigned)HW) {
            if (gc >= 0 && gc + 3 < HW) {
                v = *reinterpret_cast<const float4*>(&in[(size_t)gr * HW + gc]);
            } else {
                const float* rp = &in[(size_t)gr * HW];
                if ((unsigned)(gc + 0) < (unsigned)HW) v.x = rp[gc + 0];
                if ((unsigned)(gc + 1) < (unsigned)HW) v.y = rp[gc + 1];
                if ((unsigned)(gc + 2) < (unsigned)HW) v.z = rp[gc + 2];
                if ((unsigned)(gc + 3) < (unsigned)HW) v.w = rp[gc + 3];
            }
        }
        // threshold: keep strictly-above, else 0
        v.x = (v.x > THRESH) ? v.x : 0.f;
        v.y = (v.y > THRESH) ? v.y : 0.f;
        v.z = (v.z > THRESH) ? v.z : 0.f;
        v.w = (v.w > THRESH) ? v.w : 0.f;
        *reinterpret_cast<float4*>(&in_s[row * IN_W + col4]) = v;
    }
    __syncthreads();

    // ---------------- Phase 2: horizontal 9-max ----------------
    // For output col c (0..TX-1): window = in_s cols [c+4, c+12]
    // Process 4 outputs per thread-task using 3 float4 reads.
    for (int idx = tid; idx < IN_H * (TX / 4); idx += NTHREADS) {
        const int row = idx / (TX / 4);
        const int c   = (idx - row * (TX / 4)) * 4;
        const float* rp = &in_s[row * IN_W];
        const float4 a = *reinterpret_cast<const float4*>(&rp[c + 4]);
        const float4 b = *reinterpret_cast<const float4*>(&rp[c + 8]);
        const float4 d = *reinterpret_cast<const float4*>(&rp[c + 12]);
        // suffix maxes of a
        const float s3 = a.w;
        const float s2 = fmaxf(a.z, s3);
        const float s1 = fmaxf(a.y, s2);
        const float s0 = fmaxf(a.x, s1);
        // full max of b (shared by all four)
        const float mb = fmaxf(fmaxf(b.x, b.y), fmaxf(b.z, b.w));
        // prefix maxes of d
        const float p0 = d.x;
        const float p1 = fmaxf(p0, d.y);
        const float p2 = fmaxf(p1, d.z);
        const float p3 = fmaxf(p2, d.w);
        float4 o;
        o.x = fmaxf(fmaxf(s0, mb), p0);
        o.y = fmaxf(fmaxf(s1, mb), p1);
        o.z = fmaxf(fmaxf(s2, mb), p2);
        o.w = fmaxf(fmaxf(s3, mb), p3);
        *reinterpret_cast<float4*>(&h_s[row * TX + c]) = o;
    }
    __syncthreads();

    // ---------------- Phase 3: vertical 9-max + peak epilogue ----------------
    // 256 tasks: 32 col-groups (4 cols each) x 8 row-strips (8 rows each).
    {
        const int cg    = tid & 31;        // 0..31
        const int strip = tid >> 5;        // 0..7
        const int c  = cg * 4;
        const int r0 = strip * 8;

        // Load h_s rows r0 .. r0+15 (block A = first 8, block B = next 8)
        float4 hv[16];
#pragma unroll
        for (int j = 0; j < 16; j++)
            hv[j] = *reinterpret_cast<const float4*>(&h_s[(r0 + j) * TX + c]);

        // suffix maxes over block A in place: hv[i] = max(h[i..7])
#pragma unroll
        for (int i = 6; i >= 0; i--)
            hv[i] = f4max(hv[i], hv[i + 1]);

        float4 p = hv[8];  // running prefix max over block B
        const size_t gc = (size_t)(bx * TX + c);
#pragma unroll
        for (int r = 0; r < 8; r++) {
            if (r > 0) p = f4max(p, hv[8 + r]);
            const float4 mp = f4max(hv[r], p);   // 9-tap vertical max
            const float4 ctr = *reinterpret_cast<const float4*>(
                &in_s[(r0 + r + RAD) * IN_W + (c + 8)]);
            float4 o;
            o.x = (mp.x > 0.f && mp.x == ctr.x) ? mp.x : 0.f;
            o.y = (mp.y > 0.f && mp.y == ctr.y) ? mp.y : 0.f;
            o.z = (mp.z > 0.f && mp.z == ctr.z) ? mp.z : 0.f;
            o.w = (mp.w > 0.f && mp.w == ctr.w) ? mp.w : 0.f;
            const size_t grow = (size_t)(by * TY + r0 + r);
            *reinterpret_cast<float4*>(&out[grow * HW + gc]) = o;
        }
    }
}

extern "C" void kernel_launch(void* const* d_in, const int* in_sizes, int n_in,
                              void* d_out, int out_size)
{
    const float* in = (const float*)d_in[0];
    float* out = (float*)d_out;

    static bool attr_set = false;
    if (!attr_set) {
        cudaFuncSetAttribute(postprocess_kernel,
                             cudaFuncAttributeMaxDynamicSharedMemorySize,
                             SMEM_FLOATS * (int)sizeof(float));
        attr_set = true;
    }

    dim3 grid(HW / TX, HW / TY);   // 64 x 128
    postprocess_kernel<<<grid, NTHREADS, SMEM_FLOATS * sizeof(float)>>>(in, out);
}

// round 6
// speedup vs baseline: 2.0566x; 2.0050x over previous
#include <cuda_runtime.h>
#include <cuda_bf16.h>

#define HW     8192
#define THRESH 0.5f
#define TX     128      // output tile cols per block
#define TY     64       // output tile rows per block
#define IN_H   72       // h rows per tile (TY + 8 halo)
#define SEG_STRIDE 20   // 16 data floats + 4 pad per 16-col segment
#define H_PAD  164      // floats per h_s row: 8 segs * 20 + 4
#define NTHREADS 256

#define SMEM_BYTES (IN_H * H_PAD * (int)sizeof(float))

__device__ __forceinline__ float2 f2max(float2 a, float2 b) {
    float2 r; r.x = fmaxf(a.x, b.x); r.y = fmaxf(a.y, b.y); return r;
}

__device__ __forceinline__ float4 thresh4(float4 v) {
    v.x = (v.x > THRESH) ? v.x : 0.f;
    v.y = (v.y > THRESH) ? v.y : 0.f;
    v.z = (v.z > THRESH) ? v.z : 0.f;
    v.w = (v.w > THRESH) ? v.w : 0.f;
    return v;
}

__global__ void __launch_bounds__(NTHREADS, 4)
postprocess_kernel(const float* __restrict__ in, float* __restrict__ out)
{
    extern __shared__ float h_s[];      // IN_H x H_PAD (segmented layout)

    const int bx = blockIdx.x;          // 0..63
    const int by = blockIdx.y;          // 0..127
    const int tid = threadIdx.x;

    const int gr0 = by * TY - 4;        // first h row in global coords

    // -------- Phase A: load + threshold + horizontal 9-max -> h_s --------
    // 576 tasks: (row 0..71) x (seg 0..7), 16 h outputs per task.
    for (int t = tid; t < IN_H * 8; t += NTHREADS) {
        const int row = t >> 3;
        const int seg = t & 7;
        const int gr  = gr0 + row;
        const int cb  = bx * TX + seg * 16;      // first output col of segment
        const float* rp = in + (size_t)gr * HW;

        float4 blk[6];                           // input cols cb-4 .. cb+19
        const bool rin = (unsigned)gr < (unsigned)HW;
        const bool cin = (cb - 4 >= 0) && (cb + 19 < HW);
        if (rin && cin) {
#pragma unroll
            for (int j = 0; j < 6; j++)
                blk[j] = thresh4(*reinterpret_cast<const float4*>(&rp[cb - 4 + 4 * j]));
        } else {
#pragma unroll
            for (int j = 0; j < 6; j++) {
                const int c0 = cb - 4 + 4 * j;
                float4 v = make_float4(0.f, 0.f, 0.f, 0.f);
                if (rin) {
                    if ((unsigned)(c0 + 0) < (unsigned)HW) v.x = rp[c0 + 0];
                    if ((unsigned)(c0 + 1) < (unsigned)HW) v.y = rp[c0 + 1];
                    if ((unsigned)(c0 + 2) < (unsigned)HW) v.z = rp[c0 + 2];
                    if ((unsigned)(c0 + 3) < (unsigned)HW) v.w = rp[c0 + 3];
                }
                blk[j] = thresh4(v);
            }
        }

        float* hrow = &h_s[row * H_PAD + seg * SEG_STRIDE];
#pragma unroll
        for (int g = 0; g < 4; g++) {
            const float4 a = blk[g];
            const float4 b = blk[g + 1];
            const float4 d = blk[g + 2];
            // suffix maxes of a
            const float s3 = a.w;
            const float s2 = fmaxf(a.z, s3);
            const float s1 = fmaxf(a.y, s2);
            const float s0 = fmaxf(a.x, s1);
            // full max of b
            const float mb = fmaxf(fmaxf(b.x, b.y), fmaxf(b.z, b.w));
            // prefix maxes of d
            const float p0 = d.x;
            const float p1 = fmaxf(p0, d.y);
            const float p2 = fmaxf(p1, d.z);
            const float p3 = fmaxf(p2, d.w);
            float4 o;
            o.x = fmaxf(fmaxf(s0, mb), p0);
            o.y = fmaxf(fmaxf(s1, mb), p1);
            o.z = fmaxf(fmaxf(s2, mb), p2);
            o.w = fmaxf(fmaxf(s3, mb), p3);
            *reinterpret_cast<float4*>(&hrow[4 * g]) = o;
        }
    }
    __syncthreads();

    // -------- Phase B: vertical 9-max + peak epilogue --------
    // 512 tasks: (col-pair 0..63) x (8-row strip 0..7). float2 granularity
    // keeps the live h window at 32 registers so 4 CTAs/SM fit.
    for (int t = tid; t < 64 * 8; t += NTHREADS) {
        const int cp    = t & 63;
        const int strip = t >> 6;
        const int c  = cp * 2;           // local output col
        const int r0 = strip * 8;        // local output row base

        const int cofs = (c >> 4) * SEG_STRIDE + (c & 15);

        float2 hv[16];
#pragma unroll
        for (int j = 0; j < 16; j++)
            hv[j] = *reinterpret_cast<const float2*>(&h_s[(r0 + j) * H_PAD + cofs]);

        // suffix maxes over block A (rows 0..7): hv[i] = max(h[i..7])
#pragma unroll
        for (int i = 6; i >= 0; i--)
            hv[i] = f2max(hv[i], hv[i + 1]);

        float2 p = hv[8];                // running prefix over block B
        const size_t gc = (size_t)(bx * TX + c);
#pragma unroll
        for (int r = 0; r < 8; r++) {
            if (r > 0) p = f2max(p, hv[8 + r]);
            const float2 mp = f2max(hv[r], p);       // 9-tap vertical max
            const size_t grow = (size_t)(by * TY + r0 + r);
            // re-read + threshold center value (L1/L2 hit: same band just loaded)
            float2 ctr = __ldg(reinterpret_cast<const float2*>(&in[grow * HW + gc]));
            ctr.x = (ctr.x > THRESH) ? ctr.x : 0.f;
            ctr.y = (ctr.y > THRESH) ? ctr.y : 0.f;
            float2 o;
            o.x = (mp.x > 0.f && mp.x == ctr.x) ? mp.x : 0.f;
            o.y = (mp.y > 0.f && mp.y == ctr.y) ? mp.y : 0.f;
            *reinterpret_cast<float2*>(&out[grow * HW + gc]) = o;
        }
    }
}

extern "C" void kernel_launch(void* const* d_in, const int* in_sizes, int n_in,
                              void* d_out, int out_size)
{
    const float* in = (const float*)d_in[0];
    float* out = (float*)d_out;

    static bool attr_set = false;
    if (!attr_set) {
        cudaFuncSetAttribute(postprocess_kernel,
                             cudaFuncAttributeMaxDynamicSharedMemorySize,
                             SMEM_BYTES);
        attr_set = true;
    }

    dim3 grid(HW / TX, HW / TY);   // 64 x 128
    postprocess_kernel<<<grid, NTHREADS, SMEM_BYTES>>>(in, out);
}

// round 8
// speedup vs baseline: 2.1674x; 1.0538x over previous
#include <cuda_runtime.h>
#include <cuda_bf16.h>

#define HW     8192
#define THRESH 0.5f
#define TX     128      // output tile cols per block
#define TY     64       // output tile rows per block
#define IN_H   72       // h rows per tile (TY + 8 halo)
#define SEG_STRIDE 20   // 16 data + 4 pad: STS.128 hits all 32 banks (seg*20 mod 32 distinct)
#define H_PAD  164      // floats per h_s row: 8 segs * 20 + 4
#define NTHREADS 256

#define SMEM_BYTES (IN_H * H_PAD * (int)sizeof(float))

__device__ __forceinline__ float2 f2max(float2 a, float2 b) {
    float2 r; r.x = fmaxf(a.x, b.x); r.y = fmaxf(a.y, b.y); return r;
}

__device__ __forceinline__ float4 thresh4(float4 v) {
    v.x = (v.x > THRESH) ? v.x : 0.f;
    v.y = (v.y > THRESH) ? v.y : 0.f;
    v.z = (v.z > THRESH) ? v.z : 0.f;
    v.w = (v.w > THRESH) ? v.w : 0.f;
    return v;
}

__global__ void __launch_bounds__(NTHREADS, 4)
postprocess_kernel(const float* __restrict__ in, float* __restrict__ out)
{
    extern __shared__ float h_s[];      // IN_H x H_PAD (segmented layout)

    const int bx = blockIdx.x;          // 0..63
    const int by = blockIdx.y;          // 0..127
    const int tid = threadIdx.x;

    const int gr0 = by * TY - 4;        // first h row in global coords

    // -------- Phase A: load + threshold + horizontal 9-max -> h_s --------
    // 576 tasks: (row 0..71) x (seg 0..7), 16 h outputs per task.
    for (int t = tid; t < IN_H * 8; t += NTHREADS) {
        const int row = t >> 3;
        const int seg = t & 7;
        const int gr  = gr0 + row;
        const int cb  = bx * TX + seg * 16;      // first output col of segment
        const float* rp = in + (size_t)gr * HW;

        float4 blk[6];                           // input cols cb-4 .. cb+19
        const bool rin = (unsigned)gr < (unsigned)HW;
        const bool cin = (cb - 4 >= 0) && (cb + 19 < HW);
        if (rin && cin) {
#pragma unroll
            for (int j = 0; j < 6; j++)
                blk[j] = thresh4(*reinterpret_cast<const float4*>(&rp[cb - 4 + 4 * j]));
        } else {
#pragma unroll
            for (int j = 0; j < 6; j++) {
                const int c0 = cb - 4 + 4 * j;
                float4 v = make_float4(0.f, 0.f, 0.f, 0.f);
                if (rin) {
                    if ((unsigned)(c0 + 0) < (unsigned)HW) v.x = rp[c0 + 0];
                    if ((unsigned)(c0 + 1) < (unsigned)HW) v.y = rp[c0 + 1];
                    if ((unsigned)(c0 + 2) < (unsigned)HW) v.z = rp[c0 + 2];
                    if ((unsigned)(c0 + 3) < (unsigned)HW) v.w = rp[c0 + 3];
                }
                blk[j] = thresh4(v);
            }
        }

        float* hrow = &h_s[row * H_PAD + seg * SEG_STRIDE];
#pragma unroll
        for (int g = 0; g < 4; g++) {
            const float4 a = blk[g];
            const float4 b = blk[g + 1];
            const float4 d = blk[g + 2];
            // suffix maxes of a
            const float s3 = a.w;
            const float s2 = fmaxf(a.z, s3);
            const float s1 = fmaxf(a.y, s2);
            const float s0 = fmaxf(a.x, s1);
            // full max of b
            const float mb = fmaxf(fmaxf(b.x, b.y), fmaxf(b.z, b.w));
            // prefix maxes of d
            const float p0 = d.x;
            const float p1 = fmaxf(p0, d.y);
            const float p2 = fmaxf(p1, d.z);
            const float p3 = fmaxf(p2, d.w);
            float4 o;
            o.x = fmaxf(fmaxf(s0, mb), p0);
            o.y = fmaxf(fmaxf(s1, mb), p1);
            o.z = fmaxf(fmaxf(s2, mb), p2);
            o.w = fmaxf(fmaxf(s3, mb), p3);
            *reinterpret_cast<float4*>(&hrow[4 * g]) = o;
        }
    }
    __syncthreads();

    // -------- Phase B: vertical 9-max (3-block Gil-Werman) + epilogue --------
    // 256 tasks (exactly 1/thread): (col-pair 0..63) x (16-row strip 0..3).
    // Strip outputs rows r0..r0+15, consuming h rows r0..r0+23 (1.5x re-read
    // instead of 2x with 8-row strips).
    {
        const int cp    = tid & 63;
        const int strip = tid >> 6;
        const int c  = cp * 2;              // local output col (even -> 8B aligned)
        const int r0 = strip * 16;          // local output row base

        const int cofs = (c >> 4) * SEG_STRIDE + (c & 15);   // even: aligned LDS.64
        const float* hp = &h_s[r0 * H_PAD + cofs];

        const size_t gc = (size_t)(bx * TX + c);
        const size_t grow0 = (size_t)(by * TY + r0);

        // Block A: h rows 0..7 -> suffix maxes in place
        float2 A[8];
#pragma unroll
        for (int j = 0; j < 8; j++)
            A[j] = *reinterpret_cast<const float2*>(&hp[j * H_PAD]);
#pragma unroll
        for (int j = 6; j >= 0; j--)
            A[j] = f2max(A[j], A[j + 1]);

        // Stream block B (h rows 8..15): running prefix + emit out rows 0..7.
        // Keep B in registers for its own suffix pass afterwards.
        float2 B[8];
        float2 P;
#pragma unroll
        for (int i = 0; i < 8; i++) {
            const float2 bi = *reinterpret_cast<const float2*>(&hp[(8 + i) * H_PAD]);
            B[i] = bi;
            P = (i == 0) ? bi : f2max(P, bi);
            const float2 mp = f2max(A[i], P);   // 9-tap vertical max
            const size_t grow = grow0 + i;
            float2 ctr = __ldg(reinterpret_cast<const float2*>(&in[grow * HW + gc]));
            ctr.x = (ctr.x > THRESH) ? ctr.x : 0.f;
            ctr.y = (ctr.y > THRESH) ? ctr.y : 0.f;
            float2 o;
            o.x = (mp.x > 0.f && mp.x == ctr.x) ? mp.x : 0.f;
            o.y = (mp.y > 0.f && mp.y == ctr.y) ? mp.y : 0.f;
            *reinterpret_cast<float2*>(&out[grow * HW + gc]) = o;
        }

        // Suffix maxes over block B in place
#pragma unroll
        for (int j = 6; j >= 0; j--)
            B[j] = f2max(B[j], B[j + 1]);

        // Stream block C (h rows 16..23): running prefix + emit out rows 8..15.
#pragma unroll
        for (int i = 0; i < 8; i++) {
            const float2 ci = *reinterpret_cast<const float2*>(&hp[(16 + i) * H_PAD]);
            P = (i == 0) ? ci : f2max(P, ci);
            const float2 mp = f2max(B[i], P);
            const size_t grow = grow0 + 8 + i;
            float2 ctr = __ldg(reinterpret_cast<const float2*>(&in[grow * HW + gc]));
            ctr.x = (ctr.x > THRESH) ? ctr.x : 0.f;
            ctr.y = (ctr.y > THRESH) ? ctr.y : 0.f;
            float2 o;
            o.x = (mp.x > 0.f && mp.x == ctr.x) ? mp.x : 0.f;
            o.y = (mp.y > 0.f && mp.y == ctr.y) ? mp.y : 0.f;
            *reinterpret_cast<float2*>(&out[grow * HW + gc]) = o;
        }
    }
}

extern "C" void kernel_launch(void* const* d_in, const int* in_sizes, int n_in,
                              void* d_out, int out_size)
{
    const float* in = (const float*)d_in[0];
    float* out = (float*)d_out;

    static bool attr_set = false;
    if (!attr_set) {
        cudaFuncSetAttribute(postprocess_kernel,
                             cudaFuncAttributeMaxDynamicSharedMemorySize,
                             SMEM_BYTES);
        attr_set = true;
    }

    dim3 grid(HW / TX, HW / TY);   // 64 x 128
    postprocess_kernel<<<grid, NTHREADS, SMEM_BYTES>>>(in, out);
}